// round 11
// baseline (speedup 1.0000x reference)
#include <cuda_runtime.h>
#include <cuda_bf16.h>
#include <math.h>

// Problem constants
#define E_EXP    8
#define TOPK     2
#define N_EMBD   1024
#define FULL_D   1024
#define BS       8
#define SEQ      512

// Output layout: final_output (BS*SEQ*FULL), aux_loss (1), combined_mask (BS*E), logits (BS*E)
#define FINAL_OFF 0
#define AUX_OFF   (BS*SEQ*FULL_D)            // 4194304
#define MASK_OFF  (AUX_OFF + 1)              // 4194305
#define LOG_OFF   (MASK_OFF + BS*E_EXP)      // 4194369

// Scratch: hidden activations for 16 (b,k) pairs: 16 x 512 x 1024 floats = 32 MB
__device__ float g_hidden[(size_t)BS * TOPK * SEQ * N_EMBD];
__device__ int   g_tk_idx[BS][TOPK];
__device__ float g_tk_w[BS][TOPK];

// ---------------------------------------------------------------------------
// Router: logits, softmax, top-2, aux loss, mask. One block, 512 threads.
// ---------------------------------------------------------------------------
__global__ void router_kernel(const float* __restrict__ dec,
                              const float* __restrict__ rw,
                              const float* __restrict__ rb,
                              float* __restrict__ out)
{
    __shared__ float s_part[512];
    __shared__ float s_log[BS * E_EXP];
    __shared__ float s_gate[BS * E_EXP];
    __shared__ float s_mask[BS * E_EXP];

    int tid  = threadIdx.x;
    int pair = tid >> 3;        // 0..63  (b*8+e)
    int lane = tid & 7;
    int b    = pair >> 3;
    int e    = pair & 7;

    const float* dv = dec + b * N_EMBD;
    const float* wv = rw  + e * N_EMBD;
    float s = 0.f;
    #pragma unroll 4
    for (int j = lane; j < N_EMBD; j += 8)
        s += dv[j] * wv[j];
    s_part[tid] = s;
    __syncthreads();

    if (tid < 64) {
        float t = 0.f;
        #pragma unroll
        for (int q = 0; q < 8; q++) t += s_part[tid * 8 + q];
        t += rb[tid & 7];
        s_log[tid] = t;
    }
    __syncthreads();

    if (tid < BS) {
        int bb = tid;
        float l[E_EXP], g[E_EXP];
        float m = -1e30f;
        #pragma unroll
        for (int i = 0; i < E_EXP; i++) { l[i] = s_log[bb * E_EXP + i]; m = fmaxf(m, l[i]); }
        float sum = 0.f;
        #pragma unroll
        for (int i = 0; i < E_EXP; i++) { g[i] = __expf(l[i] - m); sum += g[i]; }
        #pragma unroll
        for (int i = 0; i < E_EXP; i++) { g[i] /= sum; s_gate[bb * E_EXP + i] = g[i]; }

        // top-2 (first occurrence wins on ties, matching lax.top_k)
        int i1 = 0;
        #pragma unroll
        for (int i = 1; i < E_EXP; i++) if (g[i] > g[i1]) i1 = i;
        int i2 = (i1 == 0) ? 1 : 0;
        #pragma unroll
        for (int i = 0; i < E_EXP; i++) if (i != i1 && g[i] > g[i2]) i2 = i;

        float ws = g[i1] + g[i2];
        g_tk_idx[bb][0] = i1;  g_tk_idx[bb][1] = i2;
        g_tk_w[bb][0] = g[i1] / ws;
        g_tk_w[bb][1] = g[i2] / ws;

        #pragma unroll
        for (int i = 0; i < E_EXP; i++) {
            float mk = (i == i1 || i == i2) ? 1.f : 0.f;
            s_mask[bb * E_EXP + i] = mk;
            out[MASK_OFF + bb * E_EXP + i] = mk;
            out[LOG_OFF  + bb * E_EXP + i] = l[i];
        }
    }
    __syncthreads();

    if (tid == 0) {
        float aux = 0.f;
        #pragma unroll
        for (int i = 0; i < E_EXP; i++) {
            float mg = 0.f, mm = 0.f;
            #pragma unroll
            for (int bb = 0; bb < BS; bb++) {
                mg += s_gate[bb * E_EXP + i];
                mm += s_mask[bb * E_EXP + i];
            }
            aux += (mg / (float)BS) * (mm / (float)BS);
        }
        out[AUX_OFF] = aux * (float)E_EXP;
    }
}

// ---------------------------------------------------------------------------
// GEMM tile config: 128x128x8 block tile, 256 threads, 8x8 per-thread tile
// ---------------------------------------------------------------------------
#define BM 128
#define BN 128
#define BK 8

// GEMM1: hidden[p] = relu(x[b] @ w1[e] + b1[e])   per pair p = b*2+k
// grid = (8, 4, 16)
__global__ __launch_bounds__(256)
void gemm1_kernel(const float* __restrict__ X,
                  const float* __restrict__ W1,
                  const float* __restrict__ B1)
{
    const int p = blockIdx.z;
    const int b = p >> 1, k = p & 1;
    const int e = g_tk_idx[b][k];

    const float* A    = X  + (size_t)b * SEQ * N_EMBD;
    const float* Bw   = W1 + (size_t)e * N_EMBD * N_EMBD;
    float*       C    = g_hidden + (size_t)p * SEQ * N_EMBD;
    const float* bias = B1 + e * N_EMBD;

    const int bm = blockIdx.y * BM;
    const int bn = blockIdx.x * BN;

    __shared__ float As[BK][BM];
    __shared__ float Bs[BK][BN];

    const int tid = threadIdx.x;
    const int tx = tid & 15, ty = tid >> 4;

    float acc[8][8];
    #pragma unroll
    for (int i = 0; i < 8; i++)
        #pragma unroll
        for (int j = 0; j < 8; j++) acc[i][j] = 0.f;

    const int arow = tid >> 1, acol = (tid & 1) * 4;
    const int brow = tid >> 5, bcol = (tid & 31) * 4;

    const float* Ap = A  + (size_t)(bm + arow) * N_EMBD + acol;
    const float* Bp = Bw + (size_t)brow * N_EMBD + bn + bcol;

    for (int kt = 0; kt < N_EMBD; kt += BK) {
        float4 a4 = *(const float4*)(Ap + kt);
        As[acol + 0][arow] = a4.x;
        As[acol + 1][arow] = a4.y;
        As[acol + 2][arow] = a4.z;
        As[acol + 3][arow] = a4.w;
        *(float4*)&Bs[brow][bcol] = *(const float4*)(Bp + (size_t)kt * N_EMBD);
        __syncthreads();

        #pragma unroll
        for (int kk = 0; kk < BK; kk++) {
            float4 a0 = *(const float4*)&As[kk][ty * 4];
            float4 a1 = *(const float4*)&As[kk][ty * 4 + 64];
            float4 b0 = *(const float4*)&Bs[kk][tx * 4];
            float4 b1v = *(const float4*)&Bs[kk][tx * 4 + 64];
            float ar[8] = {a0.x, a0.y, a0.z, a0.w, a1.x, a1.y, a1.z, a1.w};
            float br[8] = {b0.x, b0.y, b0.z, b0.w, b1v.x, b1v.y, b1v.z, b1v.w};
            #pragma unroll
            for (int i = 0; i < 8; i++)
                #pragma unroll
                for (int j = 0; j < 8; j++)
                    acc[i][j] = fmaf(ar[i], br[j], acc[i][j]);
        }
        __syncthreads();
    }

    // epilogue: bias + relu, float4 stores
    const int c0 = bn + tx * 4;
    float4 bv0 = *(const float4*)&bias[c0];
    float4 bv1 = *(const float4*)&bias[c0 + 64];
    #pragma unroll
    for (int i = 0; i < 8; i++) {
        int r = bm + ((i < 4) ? (ty * 4 + i) : (64 + ty * 4 + i - 4));
        float* crow = C + (size_t)r * N_EMBD;
        float4 v0, v1;
        v0.x = fmaxf(acc[i][0] + bv0.x, 0.f);
        v0.y = fmaxf(acc[i][1] + bv0.y, 0.f);
        v0.z = fmaxf(acc[i][2] + bv0.z, 0.f);
        v0.w = fmaxf(acc[i][3] + bv0.w, 0.f);
        v1.x = fmaxf(acc[i][4] + bv1.x, 0.f);
        v1.y = fmaxf(acc[i][5] + bv1.y, 0.f);
        v1.z = fmaxf(acc[i][6] + bv1.z, 0.f);
        v1.w = fmaxf(acc[i][7] + bv1.w, 0.f);
        *(float4*)&crow[c0]      = v0;
        *(float4*)&crow[c0 + 64] = v1;
    }
}

// GEMM2: final[b] = sum_k  w_k * (hidden[b,k] @ w2[e_k] + b2[e_k])
// B tiles pre-scaled by w_k in SMEM -> single accumulator, no races.
// grid = (8, 4, 8)
__global__ __launch_bounds__(256)
void gemm2_kernel(const float* __restrict__ W2,
                  const float* __restrict__ B2,
                  float* __restrict__ out)
{
    const int b = blockIdx.z;
    const int bm = blockIdx.y * BM;
    const int bn = blockIdx.x * BN;

    __shared__ float As[BK][BM];
    __shared__ float Bs[BK][BN];

    const int tid = threadIdx.x;
    const int tx = tid & 15, ty = tid >> 4;

    float acc[8][8];
    #pragma unroll
    for (int i = 0; i < 8; i++)
        #pragma unroll
        for (int j = 0; j < 8; j++) acc[i][j] = 0.f;

    const int arow = tid >> 1, acol = (tid & 1) * 4;
    const int brow = tid >> 5, bcol = (tid & 31) * 4;

    for (int k = 0; k < TOPK; k++) {
        const int   e  = g_tk_idx[b][k];
        const float wk = g_tk_w[b][k];
        const float* A  = g_hidden + (size_t)(b * TOPK + k) * SEQ * N_EMBD;
        const float* Bw = W2 + (size_t)e * N_EMBD * FULL_D;
        const float* Ap = A  + (size_t)(bm + arow) * N_EMBD + acol;
        const float* Bp = Bw + (size_t)brow * FULL_D + bn + bcol;

        for (int kt = 0; kt < N_EMBD; kt += BK) {
            float4 a4 = *(const float4*)(Ap + kt);
            As[acol + 0][arow] = a4.x;
            As[acol + 1][arow] = a4.y;
            As[acol + 2][arow] = a4.z;
            As[acol + 3][arow] = a4.w;
            float4 b4 = *(const float4*)(Bp + (size_t)kt * FULL_D);
            b4.x *= wk; b4.y *= wk; b4.z *= wk; b4.w *= wk;
            *(float4*)&Bs[brow][bcol] = b4;
            __syncthreads();

            #pragma unroll
            for (int kk = 0; kk < BK; kk++) {
                float4 a0 = *(const float4*)&As[kk][ty * 4];
                float4 a1 = *(const float4*)&As[kk][ty * 4 + 64];
                float4 b0 = *(const float4*)&Bs[kk][tx * 4];
                float4 b1v = *(const float4*)&Bs[kk][tx * 4 + 64];
                float ar[8] = {a0.x, a0.y, a0.z, a0.w, a1.x, a1.y, a1.z, a1.w};
                float br[8] = {b0.x, b0.y, b0.z, b0.w, b1v.x, b1v.y, b1v.z, b1v.w};
                #pragma unroll
                for (int i = 0; i < 8; i++)
                    #pragma unroll
                    for (int j = 0; j < 8; j++)
                        acc[i][j] = fmaf(ar[i], br[j], acc[i][j]);
            }
            __syncthreads();
        }
    }

    // epilogue: combined bias  sum_k w_k * b2[e_k][c]
    const int e0 = g_tk_idx[b][0], e1 = g_tk_idx[b][1];
    const float w0 = g_tk_w[b][0], w1 = g_tk_w[b][1];
    const int c0 = bn + tx * 4;
    float bias[8];
    #pragma unroll
    for (int j = 0; j < 8; j++) {
        int c = (j < 4) ? (c0 + j) : (c0 + 64 + j - 4);
        bias[j] = w0 * B2[e0 * FULL_D + c] + w1 * B2[e1 * FULL_D + c];
    }

    float* Orow = out + FINAL_OFF + (size_t)b * SEQ * FULL_D;
    #pragma unroll
    for (int i = 0; i < 8; i++) {
        int r = bm + ((i < 4) ? (ty * 4 + i) : (64 + ty * 4 + i - 4));
        float* crow = Orow + (size_t)r * FULL_D;
        float4 v0, v1;
        v0.x = acc[i][0] + bias[0];
        v0.y = acc[i][1] + bias[1];
        v0.z = acc[i][2] + bias[2];
        v0.w = acc[i][3] + bias[3];
        v1.x = acc[i][4] + bias[4];
        v1.y = acc[i][5] + bias[5];
        v1.z = acc[i][6] + bias[6];
        v1.w = acc[i][7] + bias[7];
        *(float4*)&crow[c0]      = v0;
        *(float4*)&crow[c0 + 64] = v1;
    }
}

// ---------------------------------------------------------------------------
extern "C" void kernel_launch(void* const* d_in, const int* in_sizes, int n_in,
                              void* d_out, int out_size)
{
    const float* x   = (const float*)d_in[0];
    const float* dec = (const float*)d_in[1];
    const float* rw  = (const float*)d_in[2];
    const float* rb  = (const float*)d_in[3];
    const float* w1  = (const float*)d_in[4];
    const float* w2  = (const float*)d_in[5];
    const float* b1  = (const float*)d_in[6];
    const float* b2  = (const float*)d_in[7];
    float* out = (float*)d_out;

    router_kernel<<<1, 512>>>(dec, rw, rb, out);
    gemm1_kernel<<<dim3(FULL_D / BN, SEQ / BM, BS * TOPK), 256>>>(x, w1, b1);
    gemm2_kernel<<<dim3(FULL_D / BN, SEQ / BM, BS), 256>>>(w2, b2, out);
}

// round 12
// speedup vs baseline: 1.0081x; 1.0081x over previous
#include <cuda_runtime.h>
#include <cuda_bf16.h>
#include <math.h>

// Problem constants
#define E_EXP    8
#define TOPK     2
#define N_EMBD   1024
#define FULL_D   1024
#define BS       8
#define SEQ      512

// Output layout: final_output (BS*SEQ*FULL), aux_loss (1), combined_mask (BS*E), logits (BS*E)
#define FINAL_OFF 0
#define AUX_OFF   (BS*SEQ*FULL_D)            // 4194304
#define MASK_OFF  (AUX_OFF + 1)              // 4194305
#define LOG_OFF   (MASK_OFF + BS*E_EXP)      // 4194369

// Scratch: hidden activations for 16 (b,k) pairs: 16 x 512 x 1024 floats = 32 MB
__device__ float g_hidden[(size_t)BS * TOPK * SEQ * N_EMBD];
__device__ int   g_tk_idx[BS][TOPK];
__device__ float g_tk_w[BS][TOPK];

// ---------------------------------------------------------------------------
// Router: logits, softmax, top-2, aux loss, mask. One block, 512 threads.
// ---------------------------------------------------------------------------
__global__ void router_kernel(const float* __restrict__ dec,
                              const float* __restrict__ rw,
                              const float* __restrict__ rb,
                              float* __restrict__ out)
{
    __shared__ float s_part[512];
    __shared__ float s_log[BS * E_EXP];
    __shared__ float s_gate[BS * E_EXP];
    __shared__ float s_mask[BS * E_EXP];

    int tid  = threadIdx.x;
    int pair = tid >> 3;        // 0..63  (b*8+e)
    int lane = tid & 7;
    int b    = pair >> 3;
    int e    = pair & 7;

    const float* dv = dec + b * N_EMBD;
    const float* wv = rw  + e * N_EMBD;
    float s = 0.f;
    #pragma unroll 4
    for (int j = lane; j < N_EMBD; j += 8)
        s += dv[j] * wv[j];
    s_part[tid] = s;
    __syncthreads();

    if (tid < 64) {
        float t = 0.f;
        #pragma unroll
        for (int q = 0; q < 8; q++) t += s_part[tid * 8 + q];
        t += rb[tid & 7];
        s_log[tid] = t;
    }
    __syncthreads();

    if (tid < BS) {
        int bb = tid;
        float l[E_EXP], g[E_EXP];
        float m = -1e30f;
        #pragma unroll
        for (int i = 0; i < E_EXP; i++) { l[i] = s_log[bb * E_EXP + i]; m = fmaxf(m, l[i]); }
        float sum = 0.f;
        #pragma unroll
        for (int i = 0; i < E_EXP; i++) { g[i] = __expf(l[i] - m); sum += g[i]; }
        #pragma unroll
        for (int i = 0; i < E_EXP; i++) { g[i] /= sum; s_gate[bb * E_EXP + i] = g[i]; }

        // top-2 (first occurrence wins on ties, matching lax.top_k)
        int i1 = 0;
        #pragma unroll
        for (int i = 1; i < E_EXP; i++) if (g[i] > g[i1]) i1 = i;
        int i2 = (i1 == 0) ? 1 : 0;
        #pragma unroll
        for (int i = 0; i < E_EXP; i++) if (i != i1 && g[i] > g[i2]) i2 = i;

        float ws = g[i1] + g[i2];
        g_tk_idx[bb][0] = i1;  g_tk_idx[bb][1] = i2;
        g_tk_w[bb][0] = g[i1] / ws;
        g_tk_w[bb][1] = g[i2] / ws;

        #pragma unroll
        for (int i = 0; i < E_EXP; i++) {
            float mk = (i == i1 || i == i2) ? 1.f : 0.f;
            s_mask[bb * E_EXP + i] = mk;
            out[MASK_OFF + bb * E_EXP + i] = mk;
            out[LOG_OFF  + bb * E_EXP + i] = l[i];
        }
    }
    __syncthreads();

    if (tid == 0) {
        float aux = 0.f;
        #pragma unroll
        for (int i = 0; i < E_EXP; i++) {
            float mg = 0.f, mm = 0.f;
            #pragma unroll
            for (int bb = 0; bb < BS; bb++) {
                mg += s_gate[bb * E_EXP + i];
                mm += s_mask[bb * E_EXP + i];
            }
            aux += (mg / (float)BS) * (mm / (float)BS);
        }
        out[AUX_OFF] = aux * (float)E_EXP;
    }
}

// ---------------------------------------------------------------------------
// GEMM tile config: 128x128x8 block tile, 256 threads, 8x8 per-thread tile
// ---------------------------------------------------------------------------
#define BM 128
#define BN 128
#define BK 8

// GEMM1: hidden[p] = relu(x[b] @ w1[e] + b1[e])   per pair p = b*2+k
// grid = (8, 4, 16)
__global__ __launch_bounds__(256)
void gemm1_kernel(const float* __restrict__ X,
                  const float* __restrict__ W1,
                  const float* __restrict__ B1)
{
    const int p = blockIdx.z;
    const int b = p >> 1, k = p & 1;
    const int e = g_tk_idx[b][k];

    const float* A    = X  + (size_t)b * SEQ * N_EMBD;
    const float* Bw   = W1 + (size_t)e * N_EMBD * N_EMBD;
    float*       C    = g_hidden + (size_t)p * SEQ * N_EMBD;
    const float* bias = B1 + e * N_EMBD;

    const int bm = blockIdx.y * BM;
    const int bn = blockIdx.x * BN;

    __shared__ float As[BK][BM];
    __shared__ float Bs[BK][BN];

    const int tid = threadIdx.x;
    const int tx = tid & 15, ty = tid >> 4;

    float acc[8][8];
    #pragma unroll
    for (int i = 0; i < 8; i++)
        #pragma unroll
        for (int j = 0; j < 8; j++) acc[i][j] = 0.f;

    const int arow = tid >> 1, acol = (tid & 1) * 4;
    const int brow = tid >> 5, bcol = (tid & 31) * 4;

    const float* Ap = A  + (size_t)(bm + arow) * N_EMBD + acol;
    const float* Bp = Bw + (size_t)brow * N_EMBD + bn + bcol;

    for (int kt = 0; kt < N_EMBD; kt += BK) {
        float4 a4 = *(const float4*)(Ap + kt);
        As[acol + 0][arow] = a4.x;
        As[acol + 1][arow] = a4.y;
        As[acol + 2][arow] = a4.z;
        As[acol + 3][arow] = a4.w;
        *(float4*)&Bs[brow][bcol] = *(const float4*)(Bp + (size_t)kt * N_EMBD);
        __syncthreads();

        #pragma unroll
        for (int kk = 0; kk < BK; kk++) {
            float4 a0 = *(const float4*)&As[kk][ty * 4];
            float4 a1 = *(const float4*)&As[kk][ty * 4 + 64];
            float4 b0 = *(const float4*)&Bs[kk][tx * 4];
            float4 b1v = *(const float4*)&Bs[kk][tx * 4 + 64];
            float ar[8] = {a0.x, a0.y, a0.z, a0.w, a1.x, a1.y, a1.z, a1.w};
            float br[8] = {b0.x, b0.y, b0.z, b0.w, b1v.x, b1v.y, b1v.z, b1v.w};
            #pragma unroll
            for (int i = 0; i < 8; i++)
                #pragma unroll
                for (int j = 0; j < 8; j++)
                    acc[i][j] = fmaf(ar[i], br[j], acc[i][j]);
        }
        __syncthreads();
    }

    // epilogue: bias + relu, float4 stores
    const int c0 = bn + tx * 4;
    float4 bv0 = *(const float4*)&bias[c0];
    float4 bv1 = *(const float4*)&bias[c0 + 64];
    #pragma unroll
    for (int i = 0; i < 8; i++) {
        int r = bm + ((i < 4) ? (ty * 4 + i) : (64 + ty * 4 + i - 4));
        float* crow = C + (size_t)r * N_EMBD;
        float4 v0, v1;
        v0.x = fmaxf(acc[i][0] + bv0.x, 0.f);
        v0.y = fmaxf(acc[i][1] + bv0.y, 0.f);
        v0.z = fmaxf(acc[i][2] + bv0.z, 0.f);
        v0.w = fmaxf(acc[i][3] + bv0.w, 0.f);
        v1.x = fmaxf(acc[i][4] + bv1.x, 0.f);
        v1.y = fmaxf(acc[i][5] + bv1.y, 0.f);
        v1.z = fmaxf(acc[i][6] + bv1.z, 0.f);
        v1.w = fmaxf(acc[i][7] + bv1.w, 0.f);
        *(float4*)&crow[c0]      = v0;
        *(float4*)&crow[c0 + 64] = v1;
    }
}

// GEMM2: final[b] = sum_k  w_k * (hidden[b,k] @ w2[e_k] + b2[e_k])
// B tiles pre-scaled by w_k in SMEM -> single accumulator, no races.
// grid = (8, 4, 8)
__global__ __launch_bounds__(256)
void gemm2_kernel(const float* __restrict__ W2,
                  const float* __restrict__ B2,
                  float* __restrict__ out)
{
    const int b = blockIdx.z;
    const int bm = blockIdx.y * BM;
    const int bn = blockIdx.x * BN;

    __shared__ float As[BK][BM];
    __shared__ float Bs[BK][BN];

    const int tid = threadIdx.x;
    const int tx = tid & 15, ty = tid >> 4;

    float acc[8][8];
    #pragma unroll
    for (int i = 0; i < 8; i++)
        #pragma unroll
        for (int j = 0; j < 8; j++) acc[i][j] = 0.f;

    const int arow = tid >> 1, acol = (tid & 1) * 4;
    const int brow = tid >> 5, bcol = (tid & 31) * 4;

    for (int k = 0; k < TOPK; k++) {
        const int   e  = g_tk_idx[b][k];
        const float wk = g_tk_w[b][k];
        const float* A  = g_hidden + (size_t)(b * TOPK + k) * SEQ * N_EMBD;
        const float* Bw = W2 + (size_t)e * N_EMBD * FULL_D;
        const float* Ap = A  + (size_t)(bm + arow) * N_EMBD + acol;
        const float* Bp = Bw + (size_t)brow * FULL_D + bn + bcol;

        for (int kt = 0; kt < N_EMBD; kt += BK) {
            float4 a4 = *(const float4*)(Ap + kt);
            As[acol + 0][arow] = a4.x;
            As[acol + 1][arow] = a4.y;
            As[acol + 2][arow] = a4.z;
            As[acol + 3][arow] = a4.w;
            float4 b4 = *(const float4*)(Bp + (size_t)kt * FULL_D);
            b4.x *= wk; b4.y *= wk; b4.z *= wk; b4.w *= wk;
            *(float4*)&Bs[brow][bcol] = b4;
            __syncthreads();

            #pragma unroll
            for (int kk = 0; kk < BK; kk++) {
                float4 a0 = *(const float4*)&As[kk][ty * 4];
                float4 a1 = *(const float4*)&As[kk][ty * 4 + 64];
                float4 b0 = *(const float4*)&Bs[kk][tx * 4];
                float4 b1v = *(const float4*)&Bs[kk][tx * 4 + 64];
                float ar[8] = {a0.x, a0.y, a0.z, a0.w, a1.x, a1.y, a1.z, a1.w};
                float br[8] = {b0.x, b0.y, b0.z, b0.w, b1v.x, b1v.y, b1v.z, b1v.w};
                #pragma unroll
                for (int i = 0; i < 8; i++)
                    #pragma unroll
                    for (int j = 0; j < 8; j++)
                        acc[i][j] = fmaf(ar[i], br[j], acc[i][j]);
            }
            __syncthreads();
        }
    }

    // epilogue: combined bias  sum_k w_k * b2[e_k][c]
    const int e0 = g_tk_idx[b][0], e1 = g_tk_idx[b][1];
    const float w0 = g_tk_w[b][0], w1 = g_tk_w[b][1];
    const int c0 = bn + tx * 4;
    float bias[8];
    #pragma unroll
    for (int j = 0; j < 8; j++) {
        int c = (j < 4) ? (c0 + j) : (c0 + 64 + j - 4);
        bias[j] = w0 * B2[e0 * FULL_D + c] + w1 * B2[e1 * FULL_D + c];
    }

    float* Orow = out + FINAL_OFF + (size_t)b * SEQ * FULL_D;
    #pragma unroll
    for (int i = 0; i < 8; i++) {
        int r = bm + ((i < 4) ? (ty * 4 + i) : (64 + ty * 4 + i - 4));
        float* crow = Orow + (size_t)r * FULL_D;
        float4 v0, v1;
        v0.x = acc[i][0] + bias[0];
        v0.y = acc[i][1] + bias[1];
        v0.z = acc[i][2] + bias[2];
        v0.w = acc[i][3] + bias[3];
        v1.x = acc[i][4] + bias[4];
        v1.y = acc[i][5] + bias[5];
        v1.z = acc[i][6] + bias[6];
        v1.w = acc[i][7] + bias[7];
        *(float4*)&crow[c0]      = v0;
        *(float4*)&crow[c0 + 64] = v1;
    }
}

// ---------------------------------------------------------------------------
extern "C" void kernel_launch(void* const* d_in, const int* in_sizes, int n_in,
                              void* d_out, int out_size)
{
    const float* x   = (const float*)d_in[0];
    const float* dec = (const float*)d_in[1];
    const float* rw  = (const float*)d_in[2];
    const float* rb  = (const float*)d_in[3];
    const float* w1  = (const float*)d_in[4];
    const float* w2  = (const float*)d_in[5];
    const float* b1  = (const float*)d_in[6];
    const float* b2  = (const float*)d_in[7];
    float* out = (float*)d_out;

    router_kernel<<<1, 512>>>(dec, rw, rb, out);
    gemm1_kernel<<<dim3(FULL_D / BN, SEQ / BM, BS * TOPK), 256>>>(x, w1, b1);
    gemm2_kernel<<<dim3(FULL_D / BN, SEQ / BM, BS), 256>>>(w2, b2, out);
}

// round 13
// speedup vs baseline: 1.0095x; 1.0014x over previous
#include <cuda_runtime.h>
#include <cuda_bf16.h>
#include <math.h>

// Problem constants
#define E_EXP    8
#define TOPK     2
#define N_EMBD   1024
#define FULL_D   1024
#define BS       8
#define SEQ      512

// Output layout: final_output (BS*SEQ*FULL), aux_loss (1), combined_mask (BS*E), logits (BS*E)
#define FINAL_OFF 0
#define AUX_OFF   (BS*SEQ*FULL_D)            // 4194304
#define MASK_OFF  (AUX_OFF + 1)              // 4194305
#define LOG_OFF   (MASK_OFF + BS*E_EXP)      // 4194369

// Scratch: hidden activations for 16 (b,k) pairs: 16 x 512 x 1024 floats = 32 MB
__device__ float g_hidden[(size_t)BS * TOPK * SEQ * N_EMBD];
__device__ int   g_tk_idx[BS][TOPK];
__device__ float g_tk_w[BS][TOPK];

// ---------------------------------------------------------------------------
// Router: logits, softmax, top-2, aux loss, mask. One block, 512 threads.
// ---------------------------------------------------------------------------
__global__ void router_kernel(const float* __restrict__ dec,
                              const float* __restrict__ rw,
                              const float* __restrict__ rb,
                              float* __restrict__ out)
{
    __shared__ float s_part[512];
    __shared__ float s_log[BS * E_EXP];
    __shared__ float s_gate[BS * E_EXP];
    __shared__ float s_mask[BS * E_EXP];

    int tid  = threadIdx.x;
    int pair = tid >> 3;        // 0..63  (b*8+e)
    int lane = tid & 7;
    int b    = pair >> 3;
    int e    = pair & 7;

    const float* dv = dec + b * N_EMBD;
    const float* wv = rw  + e * N_EMBD;
    float s = 0.f;
    #pragma unroll 4
    for (int j = lane; j < N_EMBD; j += 8)
        s += dv[j] * wv[j];
    s_part[tid] = s;
    __syncthreads();

    if (tid < 64) {
        float t = 0.f;
        #pragma unroll
        for (int q = 0; q < 8; q++) t += s_part[tid * 8 + q];
        t += rb[tid & 7];
        s_log[tid] = t;
    }
    __syncthreads();

    if (tid < BS) {
        int bb = tid;
        float l[E_EXP], g[E_EXP];
        float m = -1e30f;
        #pragma unroll
        for (int i = 0; i < E_EXP; i++) { l[i] = s_log[bb * E_EXP + i]; m = fmaxf(m, l[i]); }
        float sum = 0.f;
        #pragma unroll
        for (int i = 0; i < E_EXP; i++) { g[i] = __expf(l[i] - m); sum += g[i]; }
        #pragma unroll
        for (int i = 0; i < E_EXP; i++) { g[i] /= sum; s_gate[bb * E_EXP + i] = g[i]; }

        // top-2 (first occurrence wins on ties, matching lax.top_k)
        int i1 = 0;
        #pragma unroll
        for (int i = 1; i < E_EXP; i++) if (g[i] > g[i1]) i1 = i;
        int i2 = (i1 == 0) ? 1 : 0;
        #pragma unroll
        for (int i = 0; i < E_EXP; i++) if (i != i1 && g[i] > g[i2]) i2 = i;

        float ws = g[i1] + g[i2];
        g_tk_idx[bb][0] = i1;  g_tk_idx[bb][1] = i2;
        g_tk_w[bb][0] = g[i1] / ws;
        g_tk_w[bb][1] = g[i2] / ws;

        #pragma unroll
        for (int i = 0; i < E_EXP; i++) {
            float mk = (i == i1 || i == i2) ? 1.f : 0.f;
            s_mask[bb * E_EXP + i] = mk;
            out[MASK_OFF + bb * E_EXP + i] = mk;
            out[LOG_OFF  + bb * E_EXP + i] = l[i];
        }
    }
    __syncthreads();

    if (tid == 0) {
        float aux = 0.f;
        #pragma unroll
        for (int i = 0; i < E_EXP; i++) {
            float mg = 0.f, mm = 0.f;
            #pragma unroll
            for (int bb = 0; bb < BS; bb++) {
                mg += s_gate[bb * E_EXP + i];
                mm += s_mask[bb * E_EXP + i];
            }
            aux += (mg / (float)BS) * (mm / (float)BS);
        }
        out[AUX_OFF] = aux * (float)E_EXP;
    }
}

// ---------------------------------------------------------------------------
// GEMM tile config: 128x128x8 block tile, 256 threads, 8x8 per-thread tile
// ---------------------------------------------------------------------------
#define BM 128
#define BN 128
#define BK 8

// GEMM1: hidden[p] = relu(x[b] @ w1[e] + b1[e])   per pair p = b*2+k
// grid = (8, 4, 16)
__global__ __launch_bounds__(256)
void gemm1_kernel(const float* __restrict__ X,
                  const float* __restrict__ W1,
                  const float* __restrict__ B1)
{
    const int p = blockIdx.z;
    const int b = p >> 1, k = p & 1;
    const int e = g_tk_idx[b][k];

    const float* A    = X  + (size_t)b * SEQ * N_EMBD;
    const float* Bw   = W1 + (size_t)e * N_EMBD * N_EMBD;
    float*       C    = g_hidden + (size_t)p * SEQ * N_EMBD;
    const float* bias = B1 + e * N_EMBD;

    const int bm = blockIdx.y * BM;
    const int bn = blockIdx.x * BN;

    __shared__ float As[BK][BM];
    __shared__ float Bs[BK][BN];

    const int tid = threadIdx.x;
    const int tx = tid & 15, ty = tid >> 4;

    float acc[8][8];
    #pragma unroll
    for (int i = 0; i < 8; i++)
        #pragma unroll
        for (int j = 0; j < 8; j++) acc[i][j] = 0.f;

    const int arow = tid >> 1, acol = (tid & 1) * 4;
    const int brow = tid >> 5, bcol = (tid & 31) * 4;

    const float* Ap = A  + (size_t)(bm + arow) * N_EMBD + acol;
    const float* Bp = Bw + (size_t)brow * N_EMBD + bn + bcol;

    for (int kt = 0; kt < N_EMBD; kt += BK) {
        float4 a4 = *(const float4*)(Ap + kt);
        As[acol + 0][arow] = a4.x;
        As[acol + 1][arow] = a4.y;
        As[acol + 2][arow] = a4.z;
        As[acol + 3][arow] = a4.w;
        *(float4*)&Bs[brow][bcol] = *(const float4*)(Bp + (size_t)kt * N_EMBD);
        __syncthreads();

        #pragma unroll
        for (int kk = 0; kk < BK; kk++) {
            float4 a0 = *(const float4*)&As[kk][ty * 4];
            float4 a1 = *(const float4*)&As[kk][ty * 4 + 64];
            float4 b0 = *(const float4*)&Bs[kk][tx * 4];
            float4 b1v = *(const float4*)&Bs[kk][tx * 4 + 64];
            float ar[8] = {a0.x, a0.y, a0.z, a0.w, a1.x, a1.y, a1.z, a1.w};
            float br[8] = {b0.x, b0.y, b0.z, b0.w, b1v.x, b1v.y, b1v.z, b1v.w};
            #pragma unroll
            for (int i = 0; i < 8; i++)
                #pragma unroll
                for (int j = 0; j < 8; j++)
                    acc[i][j] = fmaf(ar[i], br[j], acc[i][j]);
        }
        __syncthreads();
    }

    // epilogue: bias + relu, float4 stores
    const int c0 = bn + tx * 4;
    float4 bv0 = *(const float4*)&bias[c0];
    float4 bv1 = *(const float4*)&bias[c0 + 64];
    #pragma unroll
    for (int i = 0; i < 8; i++) {
        int r = bm + ((i < 4) ? (ty * 4 + i) : (64 + ty * 4 + i - 4));
        float* crow = C + (size_t)r * N_EMBD;
        float4 v0, v1;
        v0.x = fmaxf(acc[i][0] + bv0.x, 0.f);
        v0.y = fmaxf(acc[i][1] + bv0.y, 0.f);
        v0.z = fmaxf(acc[i][2] + bv0.z, 0.f);
        v0.w = fmaxf(acc[i][3] + bv0.w, 0.f);
        v1.x = fmaxf(acc[i][4] + bv1.x, 0.f);
        v1.y = fmaxf(acc[i][5] + bv1.y, 0.f);
        v1.z = fmaxf(acc[i][6] + bv1.z, 0.f);
        v1.w = fmaxf(acc[i][7] + bv1.w, 0.f);
        *(float4*)&crow[c0]      = v0;
        *(float4*)&crow[c0 + 64] = v1;
    }
}

// GEMM2: final[b] = sum_k  w_k * (hidden[b,k] @ w2[e_k] + b2[e_k])
// B tiles pre-scaled by w_k in SMEM -> single accumulator, no races.
// grid = (8, 4, 8)
__global__ __launch_bounds__(256)
void gemm2_kernel(const float* __restrict__ W2,
                  const float* __restrict__ B2,
                  float* __restrict__ out)
{
    const int b = blockIdx.z;
    const int bm = blockIdx.y * BM;
    const int bn = blockIdx.x * BN;

    __shared__ float As[BK][BM];
    __shared__ float Bs[BK][BN];

    const int tid = threadIdx.x;
    const int tx = tid & 15, ty = tid >> 4;

    float acc[8][8];
    #pragma unroll
    for (int i = 0; i < 8; i++)
        #pragma unroll
        for (int j = 0; j < 8; j++) acc[i][j] = 0.f;

    const int arow = tid >> 1, acol = (tid & 1) * 4;
    const int brow = tid >> 5, bcol = (tid & 31) * 4;

    for (int k = 0; k < TOPK; k++) {
        const int   e  = g_tk_idx[b][k];
        const float wk = g_tk_w[b][k];
        const float* A  = g_hidden + (size_t)(b * TOPK + k) * SEQ * N_EMBD;
        const float* Bw = W2 + (size_t)e * N_EMBD * FULL_D;
        const float* Ap = A  + (size_t)(bm + arow) * N_EMBD + acol;
        const float* Bp = Bw + (size_t)brow * FULL_D + bn + bcol;

        for (int kt = 0; kt < N_EMBD; kt += BK) {
            float4 a4 = *(const float4*)(Ap + kt);
            As[acol + 0][arow] = a4.x;
            As[acol + 1][arow] = a4.y;
            As[acol + 2][arow] = a4.z;
            As[acol + 3][arow] = a4.w;
            float4 b4 = *(const float4*)(Bp + (size_t)kt * FULL_D);
            b4.x *= wk; b4.y *= wk; b4.z *= wk; b4.w *= wk;
            *(float4*)&Bs[brow][bcol] = b4;
            __syncthreads();

            #pragma unroll
            for (int kk = 0; kk < BK; kk++) {
                float4 a0 = *(const float4*)&As[kk][ty * 4];
                float4 a1 = *(const float4*)&As[kk][ty * 4 + 64];
                float4 b0 = *(const float4*)&Bs[kk][tx * 4];
                float4 b1v = *(const float4*)&Bs[kk][tx * 4 + 64];
                float ar[8] = {a0.x, a0.y, a0.z, a0.w, a1.x, a1.y, a1.z, a1.w};
                float br[8] = {b0.x, b0.y, b0.z, b0.w, b1v.x, b1v.y, b1v.z, b1v.w};
                #pragma unroll
                for (int i = 0; i < 8; i++)
                    #pragma unroll
                    for (int j = 0; j < 8; j++)
                        acc[i][j] = fmaf(ar[i], br[j], acc[i][j]);
            }
            __syncthreads();
        }
    }

    // epilogue: combined bias  sum_k w_k * b2[e_k][c]
    const int e0 = g_tk_idx[b][0], e1 = g_tk_idx[b][1];
    const float w0 = g_tk_w[b][0], w1 = g_tk_w[b][1];
    const int c0 = bn + tx * 4;
    float bias[8];
    #pragma unroll
    for (int j = 0; j < 8; j++) {
        int c = (j < 4) ? (c0 + j) : (c0 + 64 + j - 4);
        bias[j] = w0 * B2[e0 * FULL_D + c] + w1 * B2[e1 * FULL_D + c];
    }

    float* Orow = out + FINAL_OFF + (size_t)b * SEQ * FULL_D;
    #pragma unroll
    for (int i = 0; i < 8; i++) {
        int r = bm + ((i < 4) ? (ty * 4 + i) : (64 + ty * 4 + i - 4));
        float* crow = Orow + (size_t)r * FULL_D;
        float4 v0, v1;
        v0.x = acc[i][0] + bias[0];
        v0.y = acc[i][1] + bias[1];
        v0.z = acc[i][2] + bias[2];
        v0.w = acc[i][3] + bias[3];
        v1.x = acc[i][4] + bias[4];
        v1.y = acc[i][5] + bias[5];
        v1.z = acc[i][6] + bias[6];
        v1.w = acc[i][7] + bias[7];
        *(float4*)&crow[c0]      = v0;
        *(float4*)&crow[c0 + 64] = v1;
    }
}

// ---------------------------------------------------------------------------
extern "C" void kernel_launch(void* const* d_in, const int* in_sizes, int n_in,
                              void* d_out, int out_size)
{
    const float* x   = (const float*)d_in[0];
    const float* dec = (const float*)d_in[1];
    const float* rw  = (const float*)d_in[2];
    const float* rb  = (const float*)d_in[3];
    const float* w1  = (const float*)d_in[4];
    const float* w2  = (const float*)d_in[5];
    const float* b1  = (const float*)d_in[6];
    const float* b2  = (const float*)d_in[7];
    float* out = (float*)d_out;

    router_kernel<<<1, 512>>>(dec, rw, rb, out);
    gemm1_kernel<<<dim3(FULL_D / BN, SEQ / BM, BS * TOPK), 256>>>(x, w1, b1);
    gemm2_kernel<<<dim3(FULL_D / BN, SEQ / BM, BS), 256>>>(w2, b2, out);
}